// round 5
// baseline (speedup 1.0000x reference)
#include <cuda_runtime.h>
#include <cuda_fp16.h>
#include <cuda_bf16.h>
#include <cstdint>
#include <cstddef>

// Problem dims
#define BN   8192
#define DK   4096
#define HN   8192
#define NEXP 2

#define XSCALE 256.0f
#define WSCALE 1024.0f
#define INV_S  (1.0f / (256.0f * 1024.0f))
#define LN4    1.3862943611198906f   // conf<0.8  <=>  |t0-t1| < ln4

// GEMM tiling
#define TBM 128
#define TBN 128
#define TBK 32
#define KCHUNKS (DK / TBK)           // 128
#define SH_K 48                      // 32 data halves + 16 pad (96B rows, 16B-multiple)
#define A_BYTES (4 * 128 * SH_K * 2) // 2 stages x 2 parts
#define SMEM_BYTES (2 * A_BYTES)     // 98304

// ---------------------------------------------------------------------------
// Device scratch (static; no allocation allowed)
// ---------------------------------------------------------------------------
__device__ __half g_xhi[(size_t)BN * DK];
__device__ __half g_xlo[(size_t)BN * DK];
__device__ __half g_whi[(size_t)NEXP * HN * DK];   // [e][H][D] (transposed)
__device__ __half g_wlo[(size_t)NEXP * HN * DK];
__device__ float  g_h  [(size_t)NEXP * BN * HN];   // relu hidden, fp32

// ---------------------------------------------------------------------------
// Helpers
// ---------------------------------------------------------------------------
__device__ __forceinline__ void cp_async16(uint32_t dst, const void* src) {
    asm volatile("cp.async.cg.shared.global [%0], [%1], 16;"
                 :: "r"(dst), "l"(__cvta_generic_to_global(src)));
}
__device__ __forceinline__ void cp_commit() {
    asm volatile("cp.async.commit_group;" ::: "memory");
}
__device__ __forceinline__ void cp_wait1() {
    asm volatile("cp.async.wait_group 1;" ::: "memory");
}
__device__ __forceinline__ void cp_wait0() {
    asm volatile("cp.async.wait_group 0;" ::: "memory");
}
__device__ __forceinline__ uint32_t smem_u32(const void* p) {
    uint32_t a;
    asm("{ .reg .u64 t; cvta.to.shared.u64 t, %1; cvt.u32.u64 %0, t; }"
        : "=r"(a) : "l"(p));
    return a;
}
__device__ __forceinline__ uint32_t ld2(const __half* p) {
    return *reinterpret_cast<const uint32_t*>(p);
}

#define MMA(c, a, b) asm volatile( \
    "mma.sync.aligned.m16n8k16.row.col.f32.f16.f16.f32 " \
    "{%0,%1,%2,%3}, {%4,%5,%6,%7}, {%8,%9}, {%0,%1,%2,%3};" \
    : "+f"((c)[0]), "+f"((c)[1]), "+f"((c)[2]), "+f"((c)[3]) \
    : "r"((a)[0]), "r"((a)[1]), "r"((a)[2]), "r"((a)[3]), \
      "r"((b)[0]), "r"((b)[1]))

// ---------------------------------------------------------------------------
// Kernel 1: split x (fp32 -> fp16 hi/lo, scaled by XSCALE)
// ---------------------------------------------------------------------------
__global__ void split_x_kernel(const float* __restrict__ x) {
    size_t i = (size_t)blockIdx.x * blockDim.x + threadIdx.x;   // over BN*DK/4
    float4 v = reinterpret_cast<const float4*>(x)[i];
    float a0 = v.x * XSCALE, a1 = v.y * XSCALE;
    float a2 = v.z * XSCALE, a3 = v.w * XSCALE;
    __half h0 = __float2half_rn(a0), h1 = __float2half_rn(a1);
    __half h2 = __float2half_rn(a2), h3 = __float2half_rn(a3);
    __half l0 = __float2half_rn(a0 - __half2float(h0));
    __half l1 = __float2half_rn(a1 - __half2float(h1));
    __half l2 = __float2half_rn(a2 - __half2float(h2));
    __half l3 = __float2half_rn(a3 - __half2float(h3));
    __half2* ph = reinterpret_cast<__half2*>(g_xhi + 4 * i);
    __half2* pl = reinterpret_cast<__half2*>(g_xlo + 4 * i);
    ph[0] = __halves2half2(h0, h1); ph[1] = __halves2half2(h2, h3);
    pl[0] = __halves2half2(l0, l1); pl[1] = __halves2half2(l2, l3);
}

// ---------------------------------------------------------------------------
// Kernel 2: split + transpose w1 ([D][H] fp32 -> [H][D] fp16 hi/lo, x WSCALE)
// grid (H/32, D/32, 2), block (32, 8)
// ---------------------------------------------------------------------------
__global__ void split_w_kernel(const float* __restrict__ tw,
                               const float* __restrict__ fw) {
    __shared__ float tile[32][33];
    int e = blockIdx.z;
    const float* w = e ? fw : tw;
    __half* ohi = g_whi + (size_t)e * HN * DK;
    __half* olo = g_wlo + (size_t)e * HN * DK;
    int h0 = blockIdx.x * 32, d0 = blockIdx.y * 32;
    int tx = threadIdx.x, ty = threadIdx.y;
    #pragma unroll
    for (int i = ty; i < 32; i += 8)
        tile[i][tx] = w[(size_t)(d0 + i) * HN + h0 + tx];
    __syncthreads();
    #pragma unroll
    for (int i = ty; i < 32; i += 8) {
        float v = tile[tx][i] * WSCALE;                // = w[d0+tx][h0+i]
        __half hi = __float2half_rn(v);
        __half lo = __float2half_rn(v - __half2float(hi));
        size_t o = (size_t)(h0 + i) * DK + d0 + tx;
        ohi[o] = hi;
        olo[o] = lo;
    }
}

// ---------------------------------------------------------------------------
// Kernel 3: layer-1 GEMM, fp16x3 split on HMMA, relu -> g_h (fp32)
// grid (HN/128, BN/128, 2), 256 threads, dynamic smem SMEM_BYTES
// ---------------------------------------------------------------------------
__global__ void __launch_bounds__(256, 1)
gemm1_kernel(const float* __restrict__ b1t, const float* __restrict__ b1f) {
    extern __shared__ __half sm[];
    const int e  = blockIdx.z;
    const int m0 = blockIdx.y * TBM;
    const int n0 = blockIdx.x * TBN;
    const float* b1 = e ? b1f : b1t;
    const __half* wh = g_whi + (size_t)e * HN * DK;
    const __half* wl = g_wlo + (size_t)e * HN * DK;

    __half* sA = sm;                         // [stage][part][128][SH_K]
    __half* sB = sm + 4 * 128 * SH_K;        // [stage][part][128][SH_K]
    const uint32_t smA = smem_u32(sA);
    const uint32_t smB = smem_u32(sB);

    const int t    = threadIdx.x;
    const int lane = t & 31;
    const int wid  = t >> 5;
    const int gid  = lane >> 2;
    const int tig  = lane & 3;
    const int m_off = (wid >> 2) * 64;       // 2 warps in M
    const int n_off = (wid & 3) * 32;        // 4 warps in N

    float acc[4][4][4];
    #pragma unroll
    for (int i = 0; i < 4; ++i)
        #pragma unroll
        for (int j = 0; j < 4; ++j)
            #pragma unroll
            for (int k = 0; k < 4; ++k) acc[i][j][k] = 0.0f;

    // Stage loader: 4 regions (Ahi, Alo, Bhi, Blo), 512 x 16B chunks each
    auto load_stage = [&](int stage, int kt) {
        int kk = kt * TBK;
        #pragma unroll
        for (int jj = 0; jj < 8; ++jj) {
            int c      = t + jj * 256;
            int region = c >> 9;
            int within = c & 511;
            int row    = within >> 2;
            int col    = within & 3;           // 16B chunk within 64B row
            const __half* src;
            uint32_t dst;
            int soff = ((stage * 2 + (region & 1)) * 128 + row) * SH_K + col * 8;
            if (region == 0) {
                src = g_xhi + (size_t)(m0 + row) * DK + kk + col * 8;
                dst = smA + soff * 2;
            } else if (region == 1) {
                src = g_xlo + (size_t)(m0 + row) * DK + kk + col * 8;
                dst = smA + soff * 2;
            } else if (region == 2) {
                src = wh + (size_t)(n0 + row) * DK + kk + col * 8;
                dst = smB + soff * 2;
            } else {
                src = wl + (size_t)(n0 + row) * DK + kk + col * 8;
                dst = smB + soff * 2;
            }
            cp_async16(dst, src);
        }
    };

    int stage = 0;
    load_stage(0, 0);
    cp_commit();

    for (int kt = 0; kt < KCHUNKS; ++kt) {
        if (kt + 1 < KCHUNKS) {
            load_stage(stage ^ 1, kt + 1);
            cp_commit();
            cp_wait1();
        } else {
            cp_wait0();
        }
        __syncthreads();

        const __half* Ah = sA + (stage * 2 + 0) * 128 * SH_K;
        const __half* Al = sA + (stage * 2 + 1) * 128 * SH_K;
        const __half* Bh = sB + (stage * 2 + 0) * 128 * SH_K;
        const __half* Bl = sB + (stage * 2 + 1) * 128 * SH_K;

        #pragma unroll
        for (int ks = 0; ks < 2; ++ks) {
            const int kb = ks * 16;
            uint32_t ah[4][4], al[4][4];
            #pragma unroll
            for (int i = 0; i < 4; ++i) {
                int r = m_off + i * 16 + gid;
                const __half* p0 = Ah + r * SH_K + kb + tig * 2;
                ah[i][0] = ld2(p0);
                ah[i][1] = ld2(p0 + 8 * SH_K);
                ah[i][2] = ld2(p0 + 8);
                ah[i][3] = ld2(p0 + 8 * SH_K + 8);
                const __half* p1 = Al + r * SH_K + kb + tig * 2;
                al[i][0] = ld2(p1);
                al[i][1] = ld2(p1 + 8 * SH_K);
                al[i][2] = ld2(p1 + 8);
                al[i][3] = ld2(p1 + 8 * SH_K + 8);
            }
            uint32_t bh[4][2], bl[4][2];
            #pragma unroll
            for (int j = 0; j < 4; ++j) {
                int r = n_off + j * 8 + gid;
                const __half* p0 = Bh + r * SH_K + kb + tig * 2;
                bh[j][0] = ld2(p0);
                bh[j][1] = ld2(p0 + 8);
                const __half* p1 = Bl + r * SH_K + kb + tig * 2;
                bl[j][0] = ld2(p1);
                bl[j][1] = ld2(p1 + 8);
            }
            #pragma unroll
            for (int i = 0; i < 4; ++i)
                #pragma unroll
                for (int j = 0; j < 4; ++j) {
                    MMA(acc[i][j], ah[i], bh[j]);   // hi*hi
                    MMA(acc[i][j], ah[i], bl[j]);   // hi*lo
                    MMA(acc[i][j], al[i], bh[j]);   // lo*hi
                }
        }
        __syncthreads();
        stage ^= 1;
    }

    // Epilogue: h = relu(acc*INV_S + b1), fp32 to g_h
    float* hout = g_h + (size_t)e * BN * HN;
    #pragma unroll
    for (int i = 0; i < 4; ++i) {
        int r0 = m0 + m_off + i * 16 + gid;
        #pragma unroll
        for (int j = 0; j < 4; ++j) {
            int c0 = n0 + n_off + j * 8 + tig * 2;
            float bb0 = b1[c0], bb1 = b1[c0 + 1];
            float v0 = fmaxf(acc[i][j][0] * INV_S + bb0, 0.0f);
            float v1 = fmaxf(acc[i][j][1] * INV_S + bb1, 0.0f);
            float v2 = fmaxf(acc[i][j][2] * INV_S + bb0, 0.0f);
            float v3 = fmaxf(acc[i][j][3] * INV_S + bb1, 0.0f);
            hout[(size_t)r0 * HN + c0]            = v0;
            hout[(size_t)r0 * HN + c0 + 1]        = v1;
            hout[(size_t)(r0 + 8) * HN + c0]      = v2;
            hout[(size_t)(r0 + 8) * HN + c0 + 1]  = v3;
        }
    }
}

// ---------------------------------------------------------------------------
// Kernel 4: layer-2 (H->2) for both experts + confidence select
// grid (BN), 256 threads
// ---------------------------------------------------------------------------
__global__ void finalize_kernel(const float* __restrict__ w2t,
                                const float* __restrict__ b2t,
                                const float* __restrict__ w2f,
                                const float* __restrict__ b2f,
                                float* __restrict__ out) {
    int b = blockIdx.x;
    const float* ht = g_h + (size_t)b * HN;
    const float* hf = g_h + (size_t)BN * HN + (size_t)b * HN;
    float t0 = 0.f, t1 = 0.f, f0 = 0.f, f1 = 0.f;
    for (int i = threadIdx.x; i < HN; i += blockDim.x) {
        float a = ht[i];
        float c = hf[i];
        float2 wt = reinterpret_cast<const float2*>(w2t)[i];
        float2 wf = reinterpret_cast<const float2*>(w2f)[i];
        t0 += a * wt.x; t1 += a * wt.y;
        f0 += c * wf.x; f1 += c * wf.y;
    }
    #pragma unroll
    for (int o = 16; o > 0; o >>= 1) {
        t0 += __shfl_xor_sync(0xFFFFFFFFu, t0, o);
        t1 += __shfl_xor_sync(0xFFFFFFFFu, t1, o);
        f0 += __shfl_xor_sync(0xFFFFFFFFu, f0, o);
        f1 += __shfl_xor_sync(0xFFFFFFFFu, f1, o);
    }
    __shared__ float red[4][8];
    int w = threadIdx.x >> 5, l = threadIdx.x & 31;
    if (l == 0) { red[0][w] = t0; red[1][w] = t1; red[2][w] = f0; red[3][w] = f1; }
    __syncthreads();
    if (threadIdx.x == 0) {
        float T0 = 0.f, T1 = 0.f, F0 = 0.f, F1 = 0.f;
        #pragma unroll
        for (int k = 0; k < 8; ++k) {
            T0 += red[0][k]; T1 += red[1][k];
            F0 += red[2][k]; F1 += red[3][k];
        }
        T0 += b2t[0]; T1 += b2t[1];
        F0 += b2f[0]; F1 += b2f[1];
        bool low = fabsf(T0 - T1) < LN4;    // conf = sigmoid(|d|) < 0.8
        out[2 * b]     = low ? F0 : T0;
        out[2 * b + 1] = low ? F1 : T1;
    }
}

// ---------------------------------------------------------------------------
// Launch
// ---------------------------------------------------------------------------
extern "C" void kernel_launch(void* const* d_in, const int* in_sizes, int n_in,
                              void* d_out, int out_size) {
    const float* x    = (const float*)d_in[0];
    const float* t_w1 = (const float*)d_in[1];
    const float* t_b1 = (const float*)d_in[2];
    const float* t_w2 = (const float*)d_in[3];
    const float* t_b2 = (const float*)d_in[4];
    const float* f_w1 = (const float*)d_in[5];
    const float* f_b1 = (const float*)d_in[6];
    const float* f_w2 = (const float*)d_in[7];
    const float* f_b2 = (const float*)d_in[8];
    float* out = (float*)d_out;

    cudaFuncSetAttribute(gemm1_kernel,
                         cudaFuncAttributeMaxDynamicSharedMemorySize, SMEM_BYTES);

    split_x_kernel<<<(size_t)BN * DK / 4 / 256, 256>>>(x);
    split_w_kernel<<<dim3(HN / 32, DK / 32, 2), dim3(32, 8)>>>(t_w1, f_w1);
    gemm1_kernel<<<dim3(HN / TBN, BN / TBM, 2), 256, SMEM_BYTES>>>(t_b1, f_b1);
    finalize_kernel<<<BN, 256>>>(t_w2, t_b2, f_w2, f_b2, out);
}

// round 9
// speedup vs baseline: 1.0575x; 1.0575x over previous
#include <cuda_runtime.h>
#include <cuda_fp16.h>
#include <cuda_bf16.h>
#include <cstdint>
#include <cstddef>

// Problem dims
#define BN   8192
#define DK   4096
#define HN   8192
#define NEXP 2

#define XSCALE 256.0f
#define WSCALE 1024.0f
#define INV_S  (1.0f / (256.0f * 1024.0f))
#define LN4    1.3862943611198906f   // conf<0.8  <=>  |t0-t1| < ln4

// GEMM tiling (baseline-PTX HMMA + ldmatrix + cp.async)
#define TBM 128
#define TBN 256
#define TBK 32
#define KCHUNKS (DK / TBK)          // 128
#define MBLK (BN / TBM)             // 64
#define NBLK (HN / TBN)             // 32
#define GROUP_M 16
#define NSTAGE 3

// Shared-memory tile: rows of 64B data + 16B pad (stride 80B).
// 5r mod 8 is a bijection -> ldmatrix 8-row groups are bank-conflict-free.
#define RS 80
#define OFF_AHI 0
#define OFF_ALO (128 * RS)          // 10240
#define OFF_BHI (256 * RS)          // 20480
#define OFF_BLO (512 * RS)          // 40960
#define STG_BYTES (768 * RS)        // 61440
#define SOFF_B1S (NSTAGE * STG_BYTES)          // 184320
#define SOFF_W2S (SOFF_B1S + 1024)             // 185344
#define SMEM_TOTAL (SOFF_W2S + 2048)           // 187392
#define NCH (NBLK * 4)              // 128 col-chunks of 64

// ---------------------------------------------------------------------------
// Device scratch (static; no allocation allowed)
// ---------------------------------------------------------------------------
__device__ __half g_xhi[(size_t)BN * DK];
__device__ __half g_xlo[(size_t)BN * DK];
__device__ __half g_whi[(size_t)NEXP * HN * DK];   // [e][H][D]
__device__ __half g_wlo[(size_t)NEXP * HN * DK];
__device__ float  g_part[(size_t)NEXP * BN * NCH * 2];

// ---------------------------------------------------------------------------
// PTX helpers (all baseline ISA: sm_75/80)
// ---------------------------------------------------------------------------
__device__ __forceinline__ void cp_async16(uint32_t dst, const void* src) {
    asm volatile("cp.async.cg.shared.global [%0], [%1], 16;"
                 :: "r"(dst), "l"(__cvta_generic_to_global(src)));
}
__device__ __forceinline__ void cp_commit() {
    asm volatile("cp.async.commit_group;" ::: "memory");
}
__device__ __forceinline__ void cp_wait1() {
    asm volatile("cp.async.wait_group 1;" ::: "memory");
}
__device__ __forceinline__ void cp_wait0() {
    asm volatile("cp.async.wait_group 0;" ::: "memory");
}
__device__ __forceinline__ uint32_t smem_u32(const void* p) {
    uint32_t a;
    asm("{ .reg .u64 t; cvta.to.shared.u64 t, %1; cvt.u32.u64 %0, t; }"
        : "=r"(a) : "l"(p));
    return a;
}
__device__ __forceinline__ void ldsm4(uint32_t (&r)[4], uint32_t addr) {
    asm volatile("ldmatrix.sync.aligned.m8n8.x4.shared.b16 {%0,%1,%2,%3}, [%4];"
                 : "=r"(r[0]), "=r"(r[1]), "=r"(r[2]), "=r"(r[3]) : "r"(addr));
}

#define MMA(c, a, b) asm volatile( \
    "mma.sync.aligned.m16n8k16.row.col.f32.f16.f16.f32 " \
    "{%0,%1,%2,%3}, {%4,%5,%6,%7}, {%8,%9}, {%0,%1,%2,%3};" \
    : "+f"((c)[0]), "+f"((c)[1]), "+f"((c)[2]), "+f"((c)[3]) \
    : "r"((a)[0]), "r"((a)[1]), "r"((a)[2]), "r"((a)[3]), \
      "r"((b)[0]), "r"((b)[1]))

// ---------------------------------------------------------------------------
// Kernel 1: split x (fp32 -> fp16 hi/lo, scaled by XSCALE)
// ---------------------------------------------------------------------------
__global__ void split_x_kernel(const float* __restrict__ x) {
    size_t i = (size_t)blockIdx.x * blockDim.x + threadIdx.x;   // BN*DK/4
    float4 v = reinterpret_cast<const float4*>(x)[i];
    float a0 = v.x * XSCALE, a1 = v.y * XSCALE;
    float a2 = v.z * XSCALE, a3 = v.w * XSCALE;
    __half h0 = __float2half_rn(a0), h1 = __float2half_rn(a1);
    __half h2 = __float2half_rn(a2), h3 = __float2half_rn(a3);
    __half l0 = __float2half_rn(a0 - __half2float(h0));
    __half l1 = __float2half_rn(a1 - __half2float(h1));
    __half l2 = __float2half_rn(a2 - __half2float(h2));
    __half l3 = __float2half_rn(a3 - __half2float(h3));
    __half2* ph = reinterpret_cast<__half2*>(g_xhi + 4 * i);
    __half2* pl = reinterpret_cast<__half2*>(g_xlo + 4 * i);
    ph[0] = __halves2half2(h0, h1); ph[1] = __halves2half2(h2, h3);
    pl[0] = __halves2half2(l0, l1); pl[1] = __halves2half2(l2, l3);
}

// ---------------------------------------------------------------------------
// Kernel 2: split + transpose w1 ([D][H] fp32 -> [H][D] fp16 hi/lo, x WSCALE)
// ---------------------------------------------------------------------------
__global__ void split_w_kernel(const float* __restrict__ tw,
                               const float* __restrict__ fw) {
    __shared__ float tile[32][33];
    int e = blockIdx.z;
    const float* w = e ? fw : tw;
    __half* ohi = g_whi + (size_t)e * HN * DK;
    __half* olo = g_wlo + (size_t)e * HN * DK;
    int h0 = blockIdx.x * 32, d0 = blockIdx.y * 32;
    int tx = threadIdx.x, ty = threadIdx.y;
    #pragma unroll
    for (int i = ty; i < 32; i += 8)
        tile[i][tx] = w[(size_t)(d0 + i) * HN + h0 + tx];
    __syncthreads();
    #pragma unroll
    for (int i = ty; i < 32; i += 8) {
        float v = tile[tx][i] * WSCALE;
        __half hi = __float2half_rn(v);
        __half lo = __float2half_rn(v - __half2float(hi));
        size_t o = (size_t)(h0 + i) * DK + d0 + tx;
        ohi[o] = hi;
        olo[o] = lo;
    }
}

// ---------------------------------------------------------------------------
// Kernel 3: fp16x3 HMMA GEMM (ldmatrix + cp.async 3-stage) + fused layer 2
// grid (MBLK*NBLK, 1, 2), 256 threads, dyn smem SMEM_TOTAL
// ---------------------------------------------------------------------------
__global__ void __launch_bounds__(256, 1)
gemm_kernel(const float* __restrict__ b1t, const float* __restrict__ b1f,
            const float* __restrict__ w2t, const float* __restrict__ w2f) {
    extern __shared__ char sm[];
    const uint32_t sb = smem_u32(sm);
    const int t    = threadIdx.x;
    const int lane = t & 31;
    const int wid  = t >> 5;
    const int e    = blockIdx.z;

    // Grouped rasterization: m fastest within GROUP_M, then n
    int bid = blockIdx.x;
    int grp = bid / (GROUP_M * NBLK);
    int rem = bid % (GROUP_M * NBLK);
    int mb  = grp * GROUP_M + (rem % GROUP_M);
    int nb  = rem / GROUP_M;
    const int m0 = mb * TBM;
    const int n0 = nb * TBN;

    const __half* wh = g_whi + (size_t)e * HN * DK;
    const __half* wl = g_wlo + (size_t)e * HN * DK;
    const float*  b1 = (e ? b1f : b1t) + n0;
    const float*  w2 = (e ? w2f : w2t) + (size_t)n0 * 2;

    float* b1s = reinterpret_cast<float*>(sm + SOFF_B1S);
    float* w2s = reinterpret_cast<float*>(sm + SOFF_W2S);
    b1s[t] = b1[t];
    w2s[t] = w2[t];
    w2s[t + 256] = w2[t + 256];

    // Warp tile 64x64: 2 warps in M x 4 warps in N
    const int m_off = (wid >> 2) * 64;
    const int n_off = (wid & 3) * 64;
    const int lrow  = lane & 15;
    const int lk    = (lane >> 4) * 16;    // k-half byte offset

    float acc[4][8][4];
    #pragma unroll
    for (int i = 0; i < 4; ++i)
        #pragma unroll
        for (int j = 0; j < 8; ++j)
            #pragma unroll
            for (int k = 0; k < 4; ++k) acc[i][j][k] = 0.0f;

    // Stage loader: 768 rows x 4 x 16B chunks = 12 cp.async per thread
    const int r4 = t >> 2, ch = t & 3;
    auto load_stage = [&](int stage, int kt) {
        const uint32_t tb = sb + (uint32_t)stage * STG_BYTES;
        const int kk = kt * TBK + ch * 8;
        #pragma unroll
        for (int jj = 0; jj < 12; ++jj) {
            int row = jj * 64 + r4;
            const __half* src;
            uint32_t off;
            if (row < 128)      { src = g_xhi + (size_t)(m0 + row) * DK;
                                  off = OFF_AHI + (uint32_t)row * RS; }
            else if (row < 256) { int lr = row - 128;
                                  src = g_xlo + (size_t)(m0 + lr) * DK;
                                  off = OFF_ALO + (uint32_t)lr * RS; }
            else if (row < 512) { int lr = row - 256;
                                  src = wh + (size_t)(n0 + lr) * DK;
                                  off = OFF_BHI + (uint32_t)lr * RS; }
            else                { int lr = row - 512;
                                  src = wl + (size_t)(n0 + lr) * DK;
                                  off = OFF_BLO + (uint32_t)lr * RS; }
            cp_async16(tb + off + ch * 16, src + kk);
        }
        cp_commit();
    };

    load_stage(0, 0);
    load_stage(1, 1);

    for (int kt = 0; kt < KCHUNKS; ++kt) {
        if (kt + 1 < KCHUNKS) cp_wait1(); else cp_wait0();
        __syncthreads();
        if (kt + 2 < KCHUNKS) load_stage((kt + 2) % NSTAGE, kt + 2);

        const uint32_t tb = sb + (uint32_t)(kt % NSTAGE) * STG_BYTES;
        const uint32_t aRow = tb + (uint32_t)(m_off + lrow) * RS + lk;
        const uint32_t bRow = tb + OFF_BHI + (uint32_t)(n_off + lrow) * RS + lk;

        #pragma unroll
        for (int ks = 0; ks < 2; ++ks) {
            const uint32_t kb = ks * 32;
            uint32_t ah[4][4], al[4][4], bh[4][4], bl[4][4];
            #pragma unroll
            for (int i = 0; i < 4; ++i) {
                ldsm4(ah[i], aRow + i * (16 * RS) + kb);
                ldsm4(al[i], aRow + OFF_ALO + i * (16 * RS) + kb);
            }
            #pragma unroll
            for (int jp = 0; jp < 4; ++jp) {
                ldsm4(bh[jp], bRow + jp * (16 * RS) + kb);
                ldsm4(bl[jp], bRow + (OFF_BLO - OFF_BHI) + jp * (16 * RS) + kb);
            }
            #pragma unroll
            for (int i = 0; i < 4; ++i)
                #pragma unroll
                for (int jp = 0; jp < 4; ++jp) {
                    // ldmatrix mats: r0=n0-7/klo, r1=n8-15/klo, r2=n0-7/khi, r3=n8-15/khi
                    uint32_t bh0[2] = { bh[jp][0], bh[jp][2] };
                    uint32_t bh1[2] = { bh[jp][1], bh[jp][3] };
                    uint32_t bl0[2] = { bl[jp][0], bl[jp][2] };
                    uint32_t bl1[2] = { bl[jp][1], bl[jp][3] };
                    MMA(acc[i][jp * 2],     ah[i], bh0);
                    MMA(acc[i][jp * 2 + 1], ah[i], bh1);
                    MMA(acc[i][jp * 2],     ah[i], bl0);
                    MMA(acc[i][jp * 2 + 1], ah[i], bl1);
                    MMA(acc[i][jp * 2],     al[i], bh0);
                    MMA(acc[i][jp * 2 + 1], al[i], bh1);
                }
        }
        __syncthreads();
    }

    // Epilogue: relu(acc*INV_S + b1) dotted with w2 -> per-(row, warp-col) partials
    const int tig = lane & 3;
    #pragma unroll
    for (int i = 0; i < 4; ++i) {
        float plo0 = 0.f, plo1 = 0.f, phi0 = 0.f, phi1 = 0.f;
        #pragma unroll
        for (int j = 0; j < 8; ++j) {
            int col = n_off + j * 8 + tig * 2;
            float bb0 = b1s[col], bb1 = b1s[col + 1];
            float h0 = fmaxf(acc[i][j][0] * INV_S + bb0, 0.0f);
            float h1 = fmaxf(acc[i][j][1] * INV_S + bb1, 0.0f);
            float h2 = fmaxf(acc[i][j][2] * INV_S + bb0, 0.0f);
            float h3 = fmaxf(acc[i][j][3] * INV_S + bb1, 0.0f);
            float w00 = w2s[2 * col],     w01 = w2s[2 * col + 1];
            float w10 = w2s[2 * col + 2], w11 = w2s[2 * col + 3];
            plo0 += h0 * w00 + h1 * w10;
            plo1 += h0 * w01 + h1 * w11;
            phi0 += h2 * w00 + h3 * w10;
            phi1 += h2 * w01 + h3 * w11;
        }
        #pragma unroll
        for (int o = 1; o <= 2; o <<= 1) {
            plo0 += __shfl_xor_sync(0xFFFFFFFFu, plo0, o);
            plo1 += __shfl_xor_sync(0xFFFFFFFFu, plo1, o);
            phi0 += __shfl_xor_sync(0xFFFFFFFFu, phi0, o);
            phi1 += __shfl_xor_sync(0xFFFFFFFFu, phi1, o);
        }
        if (tig == 0) {
            int rlo = m0 + m_off + i * 16 + (lane >> 2);
            int cch = nb * 4 + (wid & 3);
            float2* dlo = reinterpret_cast<float2*>(
                g_part + (((size_t)e * BN + rlo) * NCH + cch) * 2);
            float2* dhi = reinterpret_cast<float2*>(
                g_part + (((size_t)e * BN + rlo + 8) * NCH + cch) * 2);
            *dlo = make_float2(plo0, plo1);
            *dhi = make_float2(phi0, phi1);
        }
    }
}

// ---------------------------------------------------------------------------
// Kernel 4: reduce partials + bias + confidence select
// grid (BN/256), 256 threads
// ---------------------------------------------------------------------------
__global__ void reduce_kernel(const float* __restrict__ b2t,
                              const float* __restrict__ b2f,
                              float* __restrict__ out) {
    int row = blockIdx.x * blockDim.x + threadIdx.x;
    const float2* pt = reinterpret_cast<const float2*>(
        g_part + ((size_t)row) * NCH * 2);
    const float2* pf = reinterpret_cast<const float2*>(
        g_part + ((size_t)(BN + row)) * NCH * 2);
    float T0 = 0.f, T1 = 0.f, F0 = 0.f, F1 = 0.f;
    #pragma unroll 8
    for (int k = 0; k < NCH; ++k) {
        float2 a = pt[k], b = pf[k];
        T0 += a.x; T1 += a.y;
        F0 += b.x; F1 += b.y;
    }
    T0 += b2t[0]; T1 += b2t[1];
    F0 += b2f[0]; F1 += b2f[1];
    bool low = fabsf(T0 - T1) < LN4;     // conf = sigmoid(|d|) < 0.8
    reinterpret_cast<float2*>(out)[row] =
        low ? make_float2(F0, F1) : make_float2(T0, T1);
}

// ---------------------------------------------------------------------------
// Launch
// ---------------------------------------------------------------------------
extern "C" void kernel_launch(void* const* d_in, const int* in_sizes, int n_in,
                              void* d_out, int out_size) {
    const float* x    = (const float*)d_in[0];
    const float* t_w1 = (const float*)d_in[1];
    const float* t_b1 = (const float*)d_in[2];
    const float* t_w2 = (const float*)d_in[3];
    const float* t_b2 = (const float*)d_in[4];
    const float* f_w1 = (const float*)d_in[5];
    const float* f_b1 = (const float*)d_in[6];
    const float* f_w2 = (const float*)d_in[7];
    const float* f_b2 = (const float*)d_in[8];
    float* out = (float*)d_out;

    cudaFuncSetAttribute(gemm_kernel,
                         cudaFuncAttributeMaxDynamicSharedMemorySize, SMEM_TOTAL);

    split_x_kernel<<<(size_t)BN * DK / 4 / 256, 256>>>(x);
    split_w_kernel<<<dim3(HN / 32, DK / 32, 2), dim3(32, 8)>>>(t_w1, f_w1);
    gemm_kernel<<<dim3(MBLK * NBLK, 1, 2), 256, SMEM_TOTAL>>>(t_b1, f_b1,
                                                              t_w2, f_w2);
    reduce_kernel<<<BN / 256, 256>>>(t_b2, f_b2, out);
}

// round 11
// speedup vs baseline: 1.0616x; 1.0039x over previous
#include <cuda_runtime.h>
#include <cuda_fp16.h>
#include <cuda_bf16.h>
#include <cstdint>
#include <cstddef>

// Problem dims
#define BN   8192
#define DK   4096
#define HN   8192
#define NEXP 2

#define XSCALE 256.0f
#define WSCALE 1024.0f
#define INV_S  (1.0f / (256.0f * 1024.0f))
#define LN4    1.3862943611198906f   // conf<0.8  <=>  |t0-t1| < ln4

// GEMM tiling (baseline-PTX HMMA + ldmatrix + cp.async)
#define TBM 128
#define TBN 256
#define TBK 32
#define KCHUNKS (DK / TBK)          // 128
#define MBLK (BN / TBM)             // 64
#define NBLK (HN / TBN)             // 32
#define GROUP_M 16
#define NSTAGE 3

// Shared-memory tile: rows of 64B data + 16B pad (stride 80B).
// 5r mod 8 is a bijection -> ldmatrix 8-row groups are bank-conflict-free.
#define RS 80
#define OFF_AHI 0
#define OFF_ALO (128 * RS)          // 10240
#define OFF_BHI (256 * RS)          // 20480
#define OFF_BLO (512 * RS)          // 40960
#define STG_BYTES (768 * RS)        // 61440
#define SOFF_B1S (NSTAGE * STG_BYTES)          // 184320
#define SOFF_W2S (SOFF_B1S + 1024)             // 185344
#define SMEM_TOTAL (SOFF_W2S + 2048)           // 187392
#define NCH (NBLK * 4)              // 128 col-chunks of 64

// ---------------------------------------------------------------------------
// Device scratch (static; no allocation allowed)
// ---------------------------------------------------------------------------
__device__ __half g_xhi[(size_t)BN * DK];
__device__ __half g_xlo[(size_t)BN * DK];
__device__ __half g_whi[(size_t)NEXP * HN * DK];   // [e][H][D]
__device__ __half g_wlo[(size_t)NEXP * HN * DK];
__device__ float  g_part[(size_t)NEXP * BN * NCH * 2];

// ---------------------------------------------------------------------------
// PTX helpers (all baseline ISA: sm_75/80)
// ---------------------------------------------------------------------------
__device__ __forceinline__ void cp_async16(uint32_t dst, const void* src) {
    asm volatile("cp.async.cg.shared.global [%0], [%1], 16;"
                 :: "r"(dst), "l"(__cvta_generic_to_global(src)));
}
__device__ __forceinline__ void cp_commit() {
    asm volatile("cp.async.commit_group;" ::: "memory");
}
__device__ __forceinline__ void cp_wait1() {
    asm volatile("cp.async.wait_group 1;" ::: "memory");
}
__device__ __forceinline__ void cp_wait0() {
    asm volatile("cp.async.wait_group 0;" ::: "memory");
}
__device__ __forceinline__ uint32_t smem_u32(const void* p) {
    uint32_t a;
    asm("{ .reg .u64 t; cvta.to.shared.u64 t, %1; cvt.u32.u64 %0, t; }"
        : "=r"(a) : "l"(p));
    return a;
}
__device__ __forceinline__ void ldsm4(uint32_t (&r)[4], uint32_t addr) {
    asm volatile("ldmatrix.sync.aligned.m8n8.x4.shared.b16 {%0,%1,%2,%3}, [%4];"
                 : "=r"(r[0]), "=r"(r[1]), "=r"(r[2]), "=r"(r[3]) : "r"(addr));
}

#define MMA(c, a, b) asm volatile( \
    "mma.sync.aligned.m16n8k16.row.col.f32.f16.f16.f32 " \
    "{%0,%1,%2,%3}, {%4,%5,%6,%7}, {%8,%9}, {%0,%1,%2,%3};" \
    : "+f"((c)[0]), "+f"((c)[1]), "+f"((c)[2]), "+f"((c)[3]) \
    : "r"((a)[0]), "r"((a)[1]), "r"((a)[2]), "r"((a)[3]), \
      "r"((b)[0]), "r"((b)[1]))

// ---------------------------------------------------------------------------
// Kernel 1: split x (fp32 -> fp16 hi/lo, scaled by XSCALE)
// ---------------------------------------------------------------------------
__global__ void split_x_kernel(const float* __restrict__ x) {
    size_t i = (size_t)blockIdx.x * blockDim.x + threadIdx.x;   // BN*DK/4
    float4 v = reinterpret_cast<const float4*>(x)[i];
    float a0 = v.x * XSCALE, a1 = v.y * XSCALE;
    float a2 = v.z * XSCALE, a3 = v.w * XSCALE;
    __half h0 = __float2half_rn(a0), h1 = __float2half_rn(a1);
    __half h2 = __float2half_rn(a2), h3 = __float2half_rn(a3);
    __half l0 = __float2half_rn(a0 - __half2float(h0));
    __half l1 = __float2half_rn(a1 - __half2float(h1));
    __half l2 = __float2half_rn(a2 - __half2float(h2));
    __half l3 = __float2half_rn(a3 - __half2float(h3));
    __half2* ph = reinterpret_cast<__half2*>(g_xhi + 4 * i);
    __half2* pl = reinterpret_cast<__half2*>(g_xlo + 4 * i);
    ph[0] = __halves2half2(h0, h1); ph[1] = __halves2half2(h2, h3);
    pl[0] = __halves2half2(l0, l1); pl[1] = __halves2half2(l2, l3);
}

// ---------------------------------------------------------------------------
// Kernel 2: split + transpose w1 ([D][H] fp32 -> [H][D] fp16 hi/lo, x WSCALE)
// ---------------------------------------------------------------------------
__global__ void split_w_kernel(const float* __restrict__ tw,
                               const float* __restrict__ fw) {
    __shared__ float tile[32][33];
    int e = blockIdx.z;
    const float* w = e ? fw : tw;
    __half* ohi = g_whi + (size_t)e * HN * DK;
    __half* olo = g_wlo + (size_t)e * HN * DK;
    int h0 = blockIdx.x * 32, d0 = blockIdx.y * 32;
    int tx = threadIdx.x, ty = threadIdx.y;
    #pragma unroll
    for (int i = ty; i < 32; i += 8)
        tile[i][tx] = w[(size_t)(d0 + i) * HN + h0 + tx];
    __syncthreads();
    #pragma unroll
    for (int i = ty; i < 32; i += 8) {
        float v = tile[tx][i] * WSCALE;
        __half hi = __float2half_rn(v);
        __half lo = __float2half_rn(v - __half2float(hi));
        size_t o = (size_t)(h0 + i) * DK + d0 + tx;
        ohi[o] = hi;
        olo[o] = lo;
    }
}

// ---------------------------------------------------------------------------
// Kernel 3: fp16x3 HMMA GEMM (ldmatrix + cp.async 3-stage) + fused layer 2
// MMA issue order: 3 passes over 32 independent accumulators per pass,
// so consecutive HMMAs never share an accumulator (dep distance 32 >> L).
// grid (MBLK*NBLK, 1, 2), 256 threads, dyn smem SMEM_TOTAL
// ---------------------------------------------------------------------------
__global__ void __launch_bounds__(256, 1)
gemm_kernel(const float* __restrict__ b1t, const float* __restrict__ b1f,
            const float* __restrict__ w2t, const float* __restrict__ w2f) {
    extern __shared__ char sm[];
    const uint32_t sb = smem_u32(sm);
    const int t    = threadIdx.x;
    const int lane = t & 31;
    const int wid  = t >> 5;
    const int e    = blockIdx.z;

    // Grouped rasterization: m fastest within GROUP_M, then n
    int bid = blockIdx.x;
    int grp = bid / (GROUP_M * NBLK);
    int rem = bid % (GROUP_M * NBLK);
    int mb  = grp * GROUP_M + (rem % GROUP_M);
    int nb  = rem / GROUP_M;
    const int m0 = mb * TBM;
    const int n0 = nb * TBN;

    const __half* wh = g_whi + (size_t)e * HN * DK;
    const __half* wl = g_wlo + (size_t)e * HN * DK;
    const float*  b1 = (e ? b1f : b1t) + n0;
    const float*  w2 = (e ? w2f : w2t) + (size_t)n0 * 2;

    float* b1s = reinterpret_cast<float*>(sm + SOFF_B1S);
    float* w2s = reinterpret_cast<float*>(sm + SOFF_W2S);
    b1s[t] = b1[t];
    w2s[t] = w2[t];
    w2s[t + 256] = w2[t + 256];

    // Warp tile 64x64: 2 warps in M x 4 warps in N
    const int m_off = (wid >> 2) * 64;
    const int n_off = (wid & 3) * 64;
    const int lrow  = lane & 15;
    const int lk    = (lane >> 4) * 16;    // k-half byte offset

    float acc[4][8][4];
    #pragma unroll
    for (int i = 0; i < 4; ++i)
        #pragma unroll
        for (int j = 0; j < 8; ++j)
            #pragma unroll
            for (int k = 0; k < 4; ++k) acc[i][j][k] = 0.0f;

    // Stage loader: 768 rows x 4 x 16B chunks = 12 cp.async per thread
    const int r4 = t >> 2, ch = t & 3;
    auto load_stage = [&](int stage, int kt) {
        const uint32_t tb = sb + (uint32_t)stage * STG_BYTES;
        const int kk = kt * TBK + ch * 8;
        #pragma unroll
        for (int jj = 0; jj < 12; ++jj) {
            int row = jj * 64 + r4;
            const __half* src;
            uint32_t off;
            if (row < 128)      { src = g_xhi + (size_t)(m0 + row) * DK;
                                  off = OFF_AHI + (uint32_t)row * RS; }
            else if (row < 256) { int lr = row - 128;
                                  src = g_xlo + (size_t)(m0 + lr) * DK;
                                  off = OFF_ALO + (uint32_t)lr * RS; }
            else if (row < 512) { int lr = row - 256;
                                  src = wh + (size_t)(n0 + lr) * DK;
                                  off = OFF_BHI + (uint32_t)lr * RS; }
            else                { int lr = row - 512;
                                  src = wl + (size_t)(n0 + lr) * DK;
                                  off = OFF_BLO + (uint32_t)lr * RS; }
            cp_async16(tb + off + ch * 16, src + kk);
        }
        cp_commit();
    };

    load_stage(0, 0);
    load_stage(1, 1);

    for (int kt = 0; kt < KCHUNKS; ++kt) {
        if (kt + 1 < KCHUNKS) cp_wait1(); else cp_wait0();
        __syncthreads();
        if (kt + 2 < KCHUNKS) load_stage((kt + 2) % NSTAGE, kt + 2);

        const uint32_t tb = sb + (uint32_t)(kt % NSTAGE) * STG_BYTES;
        const uint32_t aRow = tb + (uint32_t)(m_off + lrow) * RS + lk;
        const uint32_t bRow = tb + OFF_BHI + (uint32_t)(n_off + lrow) * RS + lk;

        #pragma unroll
        for (int ks = 0; ks < 2; ++ks) {
            const uint32_t kb = ks * 32;
            uint32_t ah[4][4], al[4][4], bh[4][4], bl[4][4];
            #pragma unroll
            for (int i = 0; i < 4; ++i) {
                ldsm4(ah[i], aRow + i * (16 * RS) + kb);
                ldsm4(al[i], aRow + OFF_ALO + i * (16 * RS) + kb);
            }
            #pragma unroll
            for (int jp = 0; jp < 4; ++jp) {
                ldsm4(bh[jp], bRow + jp * (16 * RS) + kb);
                ldsm4(bl[jp], bRow + (OFF_BLO - OFF_BHI) + jp * (16 * RS) + kb);
            }
            // ldmatrix mats: r0=n0-7/klo, r1=n8-15/klo, r2=n0-7/khi, r3=n8-15/khi
            // Pass 1: hi*hi — 32 independent accumulators back-to-back
            #pragma unroll
            for (int i = 0; i < 4; ++i)
                #pragma unroll
                for (int jp = 0; jp < 4; ++jp) {
                    uint32_t b0[2] = { bh[jp][0], bh[jp][2] };
                    uint32_t b1v[2] = { bh[jp][1], bh[jp][3] };
                    MMA(acc[i][jp * 2],     ah[i], b0);
                    MMA(acc[i][jp * 2 + 1], ah[i], b1v);
                }
            // Pass 2: hi*lo
            #pragma unroll
            for (int i = 0; i < 4; ++i)
                #pragma unroll
                for (int jp = 0; jp < 4; ++jp) {
                    uint32_t b0[2] = { bl[jp][0], bl[jp][2] };
                    uint32_t b1v[2] = { bl[jp][1], bl[jp][3] };
                    MMA(acc[i][jp * 2],     ah[i], b0);
                    MMA(acc[i][jp * 2 + 1], ah[i], b1v);
                }
            // Pass 3: lo*hi
            #pragma unroll
            for (int i = 0; i < 4; ++i)
                #pragma unroll
                for (int jp = 0; jp < 4; ++jp) {
                    uint32_t b0[2] = { bh[jp][0], bh[jp][2] };
                    uint32_t b1v[2] = { bh[jp][1], bh[jp][3] };
                    MMA(acc[i][jp * 2],     al[i], b0);
                    MMA(acc[i][jp * 2 + 1], al[i], b1v);
                }
        }
        __syncthreads();
    }

    // Epilogue: relu(acc*INV_S + b1) dotted with w2 -> per-(row, warp-col) partials
    const int tig = lane & 3;
    #pragma unroll
    for (int i = 0; i < 4; ++i) {
        float plo0 = 0.f, plo1 = 0.f, phi0 = 0.f, phi1 = 0.f;
        #pragma unroll
        for (int j = 0; j < 8; ++j) {
            int col = n_off + j * 8 + tig * 2;
            float bb0 = b1s[col], bb1 = b1s[col + 1];
            float h0 = fmaxf(acc[i][j][0] * INV_S + bb0, 0.0f);
            float h1 = fmaxf(acc[i][j][1] * INV_S + bb1, 0.0f);
            float h2 = fmaxf(acc[i][j][2] * INV_S + bb0, 0.0f);
            float h3 = fmaxf(acc[i][j][3] * INV_S + bb1, 0.0f);
            float w00 = w2s[2 * col],     w01 = w2s[2 * col + 1];
            float w10 = w2s[2 * col + 2], w11 = w2s[2 * col + 3];
            plo0 += h0 * w00 + h1 * w10;
            plo1 += h0 * w01 + h1 * w11;
            phi0 += h2 * w00 + h3 * w10;
            phi1 += h2 * w01 + h3 * w11;
        }
        #pragma unroll
        for (int o = 1; o <= 2; o <<= 1) {
            plo0 += __shfl_xor_sync(0xFFFFFFFFu, plo0, o);
            plo1 += __shfl_xor_sync(0xFFFFFFFFu, plo1, o);
            phi0 += __shfl_xor_sync(0xFFFFFFFFu, phi0, o);
            phi1 += __shfl_xor_sync(0xFFFFFFFFu, phi1, o);
        }
        if (tig == 0) {
            int rlo = m0 + m_off + i * 16 + (lane >> 2);
            int cch = nb * 4 + (wid & 3);
            float2* dlo = reinterpret_cast<float2*>(
                g_part + (((size_t)e * BN + rlo) * NCH + cch) * 2);
            float2* dhi = reinterpret_cast<float2*>(
                g_part + (((size_t)e * BN + rlo + 8) * NCH + cch) * 2);
            *dlo = make_float2(plo0, plo1);
            *dhi = make_float2(phi0, phi1);
        }
    }
}

// ---------------------------------------------------------------------------
// Kernel 4: reduce partials + bias + confidence select (warp per row)
// grid (BN*32/256), 256 threads
// ---------------------------------------------------------------------------
__global__ void reduce_kernel(const float* __restrict__ b2t,
                              const float* __restrict__ b2f,
                              float* __restrict__ out) {
    int row  = (blockIdx.x * blockDim.x + threadIdx.x) >> 5;
    int lane = threadIdx.x & 31;
    const float2* pt = reinterpret_cast<const float2*>(
        g_part + ((size_t)row) * NCH * 2);
    const float2* pf = reinterpret_cast<const float2*>(
        g_part + ((size_t)(BN + row)) * NCH * 2);
    float T0 = 0.f, T1 = 0.f, F0 = 0.f, F1 = 0.f;
    #pragma unroll
    for (int k = lane; k < NCH; k += 32) {
        float2 a = pt[k], b = pf[k];
        T0 += a.x; T1 += a.y;
        F0 += b.x; F1 += b.y;
    }
    #pragma unroll
    for (int o = 16; o > 0; o >>= 1) {
        T0 += __shfl_xor_sync(0xFFFFFFFFu, T0, o);
        T1 += __shfl_xor_sync(0xFFFFFFFFu, T1, o);
        F0 += __shfl_xor_sync(0xFFFFFFFFu, F0, o);
        F1 += __shfl_xor_sync(0xFFFFFFFFu, F1, o);
    }
    if (lane == 0) {
        T0 += b2t[0]; T1 += b2t[1];
        F0 += b2f[0]; F1 += b2f[1];
        bool low = fabsf(T0 - T1) < LN4;     // conf = sigmoid(|d|) < 0.8
        reinterpret_cast<float2*>(out)[row] =
            low ? make_float2(F0, F1) : make_float2(T0, T1);
    }
}

// ---------------------------------------------------------------------------
// Launch
// ---------------------------------------------------------------------------
extern "C" void kernel_launch(void* const* d_in, const int* in_sizes, int n_in,
                              void* d_out, int out_size) {
    const float* x    = (const float*)d_in[0];
    const float* t_w1 = (const float*)d_in[1];
    const float* t_b1 = (const float*)d_in[2];
    const float* t_w2 = (const float*)d_in[3];
    const float* t_b2 = (const float*)d_in[4];
    const float* f_w1 = (const float*)d_in[5];
    const float* f_b1 = (const float*)d_in[6];
    const float* f_w2 = (const float*)d_in[7];
    const float* f_b2 = (const float*)d_in[8];
    float* out = (float*)d_out;

    cudaFuncSetAttribute(gemm_kernel,
                         cudaFuncAttributeMaxDynamicSharedMemorySize, SMEM_TOTAL);

    split_x_kernel<<<(size_t)BN * DK / 4 / 256, 256>>>(x);
    split_w_kernel<<<dim3(HN / 32, DK / 32, 2), dim3(32, 8)>>>(t_w1, f_w1);
    gemm_kernel<<<dim3(MBLK * NBLK, 1, 2), 256, SMEM_TOTAL>>>(t_b1, f_b1,
                                                              t_w2, f_w2);
    reduce_kernel<<<dim3(BN * 32 / 256), 256>>>(t_b2, f_b2, out);
}